// round 14
// baseline (speedup 1.0000x reference)
#include <cuda_runtime.h>
#include <cuda_fp16.h>
#include <math.h>

#define N_NODES 200000
#define N_EDGES 12800000
#define ALPHA   0.1f
#define DT      0.01f
#define EPS_    1e-9f
#define DIFF_   10.0f
#define HARD    1.57079632679489662f

#define EPT        16                      // edges per thread
#define N_THREADS  (N_EDGES / EPT)         // 800,000 = 3125 * 256 exactly
#define NB_EDGE    (N_THREADS / 256)       // 3125 blocks
#define N_PROD     148                     // producer blocks (<= 1 wave always)
#define NODES_PER_PROD ((N_NODES + N_PROD - 1) / N_PROD)   // 1352

// Scratch (device globals — no allocation allowed)
__device__ __half2   g_uv[N_NODES];   // pre-rotated (u,v) = e^{-i phi}(x+iy)
__device__ float2    g_sum[N_NODES];  // per-node gathered sum, atomic-accumulated
__device__ unsigned  g_ready = 0;     // producer slices completed
__device__ unsigned  g_done  = 0;     // edge blocks completed (counter reset)

// ---------------------------------------------------------------------------
// FMA-pipe sincos for |x| <= 2*pi (no MUFU). Cody-Waite pi/2 reduction,
// deg-7 sin / deg-8 cos minimax on |r| <= pi/4. Abs err ~1e-7.
// ---------------------------------------------------------------------------
__device__ __forceinline__ void sincos_poly(float x, float* sp, float* cp)
{
    float fq = rintf(x * 0.63661977236758134f);       // x * 2/pi
    int   q  = (int)fq;
    float r  = fmaf(-fq, 1.57079625129699707f, x);
    r        = fmaf(-fq, 7.54978941586159636e-8f, r);
    float r2 = r * r;

    float s = -1.9841271e-4f;
    s = fmaf(s, r2,  8.3333310e-3f);
    s = fmaf(s, r2, -1.6666667e-1f);
    s = fmaf(s * r2, r, r);

    float c =  2.44331571e-5f;
    c = fmaf(c, r2, -1.38873162e-3f);
    c = fmaf(c, r2,  4.16666418e-2f);
    c = fmaf(c, r2, -0.5f);
    c = fmaf(c, r2, 1.0f);

    float ss, cc;
    if (q & 1) { ss = c;  cc = -s; } else { ss = s; cc = c; }
    if (q & 2) { ss = -ss; cc = -cc; }
    *sp = ss; *cp = cc;
}

// ---------------------------------------------------------------------------
// K1 (fused): blocks [0, N_PROD) first produce a ~1352-node uv slice + zero
// g_sum, fence, bump g_ready. ALL blocks prefetch their src/dst int4 streams,
// then spin (nanosleep backoff) until g_ready == N_PROD, then run the
// gather / run-length-scan / atomic pipeline. Deadlock-free: wave-1 always
// contains >= 148 blocks at any occupancy, so all producers run immediately.
// Last-finishing block resets counters for the next graph replay.
// ---------------------------------------------------------------------------
__global__ void __launch_bounds__(256) fused_edge_kernel(
    const float* __restrict__ phase,
    const float* __restrict__ xy,
    const int*   __restrict__ src,
    const int*   __restrict__ dst)
{
    int bid  = blockIdx.x;
    int tid  = threadIdx.x;
    int t    = bid * 256 + tid;
    int lane = tid & 31;

    // --- producer duty (blocks 0..147, guaranteed in wave 1) ---------------
    if (bid < N_PROD) {
        int lo = bid * NODES_PER_PROD;
        int hi = lo + NODES_PER_PROD;
        if (hi > N_NODES) hi = N_NODES;
        for (int i = lo + tid; i < hi; i += 256) {
            float s, c;
            sincos_poly(phase[i], &s, &c);
            float2 p = ((const float2*)xy)[i];
            g_uv[i]  = __floats2half2_rn(fmaf(c, p.x, s * p.y), fmaf(c, p.y, -s * p.x));
            g_sum[i] = make_float2(0.0f, 0.0f);
        }
        __threadfence();
        __syncthreads();
        if (tid == 0) atomicAdd(&g_ready, 1u);
    }

    // --- prefetch edge streams (independent of g_uv) ------------------------
    int base = t * EPT;
    int4 s0 = __ldcs((const int4*)(src + base) + 0);
    int4 s1 = __ldcs((const int4*)(src + base) + 1);
    int4 s2 = __ldcs((const int4*)(src + base) + 2);
    int4 s3 = __ldcs((const int4*)(src + base) + 3);
    int4 d0 = __ldcs((const int4*)(dst + base) + 0);
    int4 d1 = __ldcs((const int4*)(dst + base) + 1);
    int4 d2 = __ldcs((const int4*)(dst + base) + 2);
    int4 d3 = __ldcs((const int4*)(dst + base) + 3);

    // --- wait for all producer slices --------------------------------------
    if (tid == 0) {
        while (*(volatile unsigned*)&g_ready < N_PROD) {
            __nanosleep(64);
        }
    }
    __syncthreads();
    __threadfence();

    int k[EPT] = { s0.x, s0.y, s0.z, s0.w,  s1.x, s1.y, s1.z, s1.w,
                   s2.x, s2.y, s2.z, s2.w,  s3.x, s3.y, s3.z, s3.w };
    int di[EPT] = { d0.x, d0.y, d0.z, d0.w,  d1.x, d1.y, d1.z, d1.w,
                    d2.x, d2.y, d2.z, d2.w,  d3.x, d3.y, d3.z, d3.w };

    __half2 h[EPT];
    #pragma unroll
    for (int e = 0; e < EPT; e++) h[e] = __ldg(&g_uv[di[e]]);

    // Run-length scan over sorted keys; interior runs flush immediately
    int   cur = k[0];
    float2 f0 = __half22float2(h[0]);
    float U = f0.x, V = f0.y;
    #pragma unroll
    for (int e = 1; e < EPT; e++) {
        float2 f = __half22float2(h[e]);
        if (k[e] != cur) {
            atomicAdd(&g_sum[cur].x, U);
            atomicAdd(&g_sum[cur].y, V);
            cur = k[e];
            U = f.x; V = f.y;
        } else {
            U += f.x; V += f.y;
        }
    }

    // Warp segmented merge of pending runs (keys nondecreasing across lanes)
    #pragma unroll
    for (int o = 1; o < 32; o <<= 1) {
        int   pk = __shfl_up_sync(0xffffffffu, cur, o);
        float pU = __shfl_up_sync(0xffffffffu, U, o);
        float pV = __shfl_up_sync(0xffffffffu, V, o);
        if (lane >= o && pk == cur) { U += pU; V += pV; }
    }
    int nk = __shfl_down_sync(0xffffffffu, cur, 1);
    if (lane == 31 || nk != cur) {
        atomicAdd(&g_sum[cur].x, U);
        atomicAdd(&g_sum[cur].y, V);
    }

    // --- completion ticket: last block resets counters for next replay -----
    __syncthreads();
    if (tid == 0) {
        unsigned tk = atomicAdd(&g_done, 1u) + 1u;
        if (tk == NB_EDGE) {
            g_ready = 0;
            g_done  = 0;
            __threadfence();
        }
    }
}

// ---------------------------------------------------------------------------
// K2: thread-per-node finalize (plain stream-order launch).
// ---------------------------------------------------------------------------
__global__ void __launch_bounds__(256) finalize_kernel(
    const float* __restrict__ phase,
    const float* __restrict__ xy,
    const float* __restrict__ xy_dot_old,
    const float* __restrict__ w,
    const float* __restrict__ amp,
    const float* __restrict__ ha,
    float*       __restrict__ out)
{
    int i = blockIdx.x * blockDim.x + threadIdx.x;
    if (i >= N_NODES) return;

    float  ph = phase[i];
    float2 p  = ((const float2*)xy)[i];
    float2 pd = ((const float2*)xy_dot_old)[i];
    float  wi = w[i];
    float  am = amp[i];
    float  hi = ha[i];

    float s, c;
    sincos_poly(ph, &s, &c);

    float r2   = fmaf(p.x, p.x, p.y * p.y);
    float a    = ALPHA * (1.0f - r2 * r2);
    float zeta = 1.0f - hi * ((pd.x + EPS_) / (fabsf(pd.x) + EPS_));
    float b    = wi / (zeta + EPS_);
    float kx   = fmaf(a, p.x, -b * p.y);
    float ky   = fmaf(b, p.x,  a * p.y);

    float2 sv = g_sum[i];

    float sum_x = fmaf(c, sv.x, -s * sv.y);
    float sum_y = fmaf(s, sv.x,  c * sv.y);

    float x_dot = fminf(fmaxf(kx + sum_x, pd.x - DIFF_), pd.x + DIFF_);
    float y_dot = fminf(fmaxf(ky + sum_y, pd.y - DIFF_), pd.y + DIFF_);

    float xn = fmaf(x_dot, DT, p.x);
    float yn = fmaf(y_dot, DT, p.y);
    float ang = fminf(fmaxf(am * yn, -HARD), HARD);

    out[i] = ang;                                              // angles
    ((float2*)(out + N_NODES))[i]     = make_float2(xn, yn);   // xy_new
    ((float2*)(out + 3 * N_NODES))[i] = p;                     // xy_dot_old_new = xy
}

extern "C" void kernel_launch(void* const* d_in, const int* in_sizes, int n_in,
                              void* d_out, int out_size)
{
    const float* xy         = (const float*)d_in[0];
    const float* xy_dot_old = (const float*)d_in[1];
    const float* phase      = (const float*)d_in[2];
    const float* w          = (const float*)d_in[3];
    const float* amplitudes = (const float*)d_in[4];
    const float* ha         = (const float*)d_in[5];
    const int*   edge_src   = (const int*)d_in[6];
    const int*   edge_dst   = (const int*)d_in[7];
    float* out = (float*)d_out;

    fused_edge_kernel<<<NB_EDGE, 256>>>(phase, xy, edge_src, edge_dst);

    int nb_nodes = (N_NODES + 255) / 256;
    finalize_kernel<<<nb_nodes, 256>>>(phase, xy, xy_dot_old, w, amplitudes,
                                       ha, out);
}

// round 15
// speedup vs baseline: 1.0852x; 1.0852x over previous
#include <cuda_runtime.h>
#include <cuda_fp16.h>
#include <math.h>

#define N_NODES 200000
#define N_EDGES 12800000
#define ALPHA   0.1f
#define DT      0.01f
#define EPS_    1e-9f
#define DIFF_   10.0f
#define HARD    1.57079632679489662f

#define EPT        16                       // edges per thread
#define N_THREADS  (N_EDGES / EPT)          // 800,000 = 3125 * 256 exactly
#define NB_EDGE    (N_THREADS / 256)        // 3125 blocks
#define N_FIN      148                      // tail finalize blocks (<< wave size)
#define NODES_PER_FIN ((N_NODES + N_FIN - 1) / N_FIN)   // 1352

// Scratch (device globals — no allocation allowed)
__device__ __half2   g_uv[N_NODES];   // pre-rotated (u,v) = e^{-i phi}(x+iy)
__device__ float2    g_sum[N_NODES];  // per-node gathered sum, atomic-accumulated
__device__ unsigned  g_done = 0;      // edge-block completion tickets
__device__ unsigned  g_fin  = 0;      // finalize-slice completions (reset logic)

// ---------------------------------------------------------------------------
// FMA-pipe sincos for |x| <= 2*pi (no MUFU). Cody-Waite pi/2 reduction,
// deg-7 sin / deg-8 cos minimax on |r| <= pi/4. Abs err ~1e-7.
// ---------------------------------------------------------------------------
__device__ __forceinline__ void sincos_poly(float x, float* sp, float* cp)
{
    float fq = rintf(x * 0.63661977236758134f);       // x * 2/pi
    int   q  = (int)fq;
    float r  = fmaf(-fq, 1.57079625129699707f, x);
    r        = fmaf(-fq, 7.54978941586159636e-8f, r);
    float r2 = r * r;

    float s = -1.9841271e-4f;
    s = fmaf(s, r2,  8.3333310e-3f);
    s = fmaf(s, r2, -1.6666667e-1f);
    s = fmaf(s * r2, r, r);

    float c =  2.44331571e-5f;
    c = fmaf(c, r2, -1.38873162e-3f);
    c = fmaf(c, r2,  4.16666418e-2f);
    c = fmaf(c, r2, -0.5f);
    c = fmaf(c, r2, 1.0f);

    float ss, cc;
    if (q & 1) { ss = c;  cc = -s; } else { ss = s; cc = c; }
    if (q & 2) { ss = -ss; cc = -cc; }
    *sp = ss; *cp = cc;
}

// ---------------------------------------------------------------------------
// Per-node finalize body (called by the tail blocks of the edge kernel).
// ---------------------------------------------------------------------------
__device__ __forceinline__ void finalize_node(
    int i,
    const float* __restrict__ phase,
    const float* __restrict__ xy,
    const float* __restrict__ xy_dot_old,
    const float* __restrict__ w,
    const float* __restrict__ amp,
    const float* __restrict__ ha,
    float*       __restrict__ out)
{
    float  ph = phase[i];
    float2 p  = ((const float2*)xy)[i];
    float2 pd = ((const float2*)xy_dot_old)[i];
    float  wi = w[i];
    float  am = amp[i];
    float  hi = ha[i];
    float2 sv = g_sum[i];

    float s, c;
    sincos_poly(ph, &s, &c);

    float sum_x = fmaf(c, sv.x, -s * sv.y);
    float sum_y = fmaf(s, sv.x,  c * sv.y);

    float r2   = fmaf(p.x, p.x, p.y * p.y);
    float a    = ALPHA * (1.0f - r2 * r2);
    float zeta = 1.0f - hi * ((pd.x + EPS_) / (fabsf(pd.x) + EPS_));
    float b    = wi / (zeta + EPS_);
    float kx   = fmaf(a, p.x, -b * p.y);
    float ky   = fmaf(b, p.x,  a * p.y);

    float x_dot = fminf(fmaxf(kx + sum_x, pd.x - DIFF_), pd.x + DIFF_);
    float y_dot = fminf(fmaxf(ky + sum_y, pd.y - DIFF_), pd.y + DIFF_);

    float xn = fmaf(x_dot, DT, p.x);
    float yn = fmaf(y_dot, DT, p.y);
    float ang = fminf(fmaxf(am * yn, -HARD), HARD);

    out[i] = ang;                                              // angles
    ((float2*)(out + N_NODES))[i]     = make_float2(xn, yn);   // xy_new
    ((float2*)(out + 3 * N_NODES))[i] = p;                     // xy_dot_old_new = xy
}

// ---------------------------------------------------------------------------
// K1: per-node prep (best-measured R12 form).
// ---------------------------------------------------------------------------
__global__ void __launch_bounds__(256) uv_kernel(
    const float* __restrict__ phase,
    const float* __restrict__ xy)
{
    int i = blockIdx.x * blockDim.x + threadIdx.x;
    if (i < N_NODES) {
        float s, c;
        sincos_poly(phase[i], &s, &c);
        float2 p = ((const float2*)xy)[i];
        g_uv[i]  = __floats2half2_rn(fmaf(c, p.x, s * p.y), fmaf(c, p.y, -s * p.x));
        g_sum[i] = make_float2(0.0f, 0.0f);
    }
}

// ---------------------------------------------------------------------------
// K2: edge pass with TAIL-fused finalize. Gather pipeline identical to the
// proven R11 version. After its atomics each block fences and takes a ticket;
// the last N_FIN=148 ticket-holders (by construction the last finishers) spin
// briefly until all 3125 tickets are taken, then finalize 1352-node slices.
// Deadlock-free: at most 148 spinners < wave size (>=592 at <=64 regs), and
// spinners never block the ticket counter. Counters self-reset for replay.
// ---------------------------------------------------------------------------
__global__ void __launch_bounds__(256) edge_kernel(
    const int*   __restrict__ src,
    const int*   __restrict__ dst,
    const float* __restrict__ phase,
    const float* __restrict__ xy,
    const float* __restrict__ xy_dot_old,
    const float* __restrict__ w,
    const float* __restrict__ amp,
    const float* __restrict__ ha,
    float*       __restrict__ out)
{
    int t = blockIdx.x * blockDim.x + threadIdx.x;   // grid is exactly N_THREADS
    int tid  = threadIdx.x;
    int lane = tid & 31;
    int base = t * EPT;

    int4 s0 = __ldcs((const int4*)(src + base) + 0);
    int4 s1 = __ldcs((const int4*)(src + base) + 1);
    int4 s2 = __ldcs((const int4*)(src + base) + 2);
    int4 s3 = __ldcs((const int4*)(src + base) + 3);
    int4 d0 = __ldcs((const int4*)(dst + base) + 0);
    int4 d1 = __ldcs((const int4*)(dst + base) + 1);
    int4 d2 = __ldcs((const int4*)(dst + base) + 2);
    int4 d3 = __ldcs((const int4*)(dst + base) + 3);

    int k[EPT] = { s0.x, s0.y, s0.z, s0.w,  s1.x, s1.y, s1.z, s1.w,
                   s2.x, s2.y, s2.z, s2.w,  s3.x, s3.y, s3.z, s3.w };
    int di[EPT] = { d0.x, d0.y, d0.z, d0.w,  d1.x, d1.y, d1.z, d1.w,
                    d2.x, d2.y, d2.z, d2.w,  d3.x, d3.y, d3.z, d3.w };

    __half2 h[EPT];
    #pragma unroll
    for (int e = 0; e < EPT; e++) h[e] = __ldg(&g_uv[di[e]]);

    // Run-length scan over sorted keys; interior runs flush immediately
    int   cur = k[0];
    float2 f0 = __half22float2(h[0]);
    float U = f0.x, V = f0.y;
    #pragma unroll
    for (int e = 1; e < EPT; e++) {
        float2 f = __half22float2(h[e]);
        if (k[e] != cur) {
            atomicAdd(&g_sum[cur].x, U);
            atomicAdd(&g_sum[cur].y, V);
            cur = k[e];
            U = f.x; V = f.y;
        } else {
            U += f.x; V += f.y;
        }
    }

    // Warp segmented merge of pending runs (keys nondecreasing across lanes)
    #pragma unroll
    for (int o = 1; o < 32; o <<= 1) {
        int   pk = __shfl_up_sync(0xffffffffu, cur, o);
        float pU = __shfl_up_sync(0xffffffffu, U, o);
        float pV = __shfl_up_sync(0xffffffffu, V, o);
        if (lane >= o && pk == cur) { U += pU; V += pV; }
    }
    int nk = __shfl_down_sync(0xffffffffu, cur, 1);
    if (lane == 31 || nk != cur) {
        atomicAdd(&g_sum[cur].x, U);
        atomicAdd(&g_sum[cur].y, V);
    }

    // --- completion ticket + tail-fused finalize ----------------------------
    __shared__ unsigned s_ticket;
    __syncthreads();                 // all atomics in this block issued
    if (tid == 0) {
        __threadfence();             // make them visible before the ticket
        s_ticket = atomicAdd(&g_done, 1u);
    }
    __syncthreads();
    unsigned ticket = s_ticket;

    if (ticket >= NB_EDGE - N_FIN) {
        // Wait until every edge block's atomics are globally visible
        if (tid == 0) {
            while (*(volatile unsigned*)&g_done < NB_EDGE) { __nanosleep(32); }
        }
        __syncthreads();
        __threadfence();

        int slice = (int)(ticket - (NB_EDGE - N_FIN));
        int lo = slice * NODES_PER_FIN;
        int hi = lo + NODES_PER_FIN;
        if (hi > N_NODES) hi = N_NODES;
        for (int i = lo + tid; i < hi; i += 256) {
            finalize_node(i, phase, xy, xy_dot_old, w, amp, ha, out);
        }

        // Reset counters for the next graph replay
        __syncthreads();
        if (tid == 0) {
            unsigned f = atomicAdd(&g_fin, 1u) + 1u;
            if (f == N_FIN) {
                g_done = 0;
                g_fin  = 0;
                __threadfence();
            }
        }
    }
}

extern "C" void kernel_launch(void* const* d_in, const int* in_sizes, int n_in,
                              void* d_out, int out_size)
{
    const float* xy         = (const float*)d_in[0];
    const float* xy_dot_old = (const float*)d_in[1];
    const float* phase      = (const float*)d_in[2];
    const float* w          = (const float*)d_in[3];
    const float* amplitudes = (const float*)d_in[4];
    const float* ha         = (const float*)d_in[5];
    const int*   edge_src   = (const int*)d_in[6];
    const int*   edge_dst   = (const int*)d_in[7];
    float* out = (float*)d_out;

    int nb_nodes = (N_NODES + 255) / 256;
    uv_kernel<<<nb_nodes, 256>>>(phase, xy);

    edge_kernel<<<NB_EDGE, 256>>>(edge_src, edge_dst, phase, xy, xy_dot_old,
                                  w, amplitudes, ha, out);
}

// round 16
// speedup vs baseline: 1.3282x; 1.2239x over previous
#include <cuda_runtime.h>
#include <cuda_fp16.h>
#include <math.h>

#define N_NODES 200000
#define N_EDGES 12800000
#define ALPHA   0.1f
#define DT      0.01f
#define EPS_    1e-9f
#define DIFF_   10.0f
#define HARD    1.57079632679489662f

#define EPT        8                       // edges per thread (smaller -> more occ)
#define N_THREADS  (N_EDGES / EPT)         // 1,600,000 = 6250 * 256 exactly

// Scratch (device globals — no allocation allowed)
__device__ __half2 g_uv[N_NODES];   // pre-rotated (u,v) = e^{-i phi}(x+iy)
__device__ float2  g_sum[N_NODES];  // per-node gathered sum, atomic-accumulated

__device__ __forceinline__ void pdl_wait()    { asm volatile("griddepcontrol.wait;" ::: "memory"); }
__device__ __forceinline__ void pdl_trigger() { asm volatile("griddepcontrol.launch_dependents;" ::: "memory"); }

// ---------------------------------------------------------------------------
// FMA-pipe sincos for |x| <= 2*pi (no MUFU). Cody-Waite pi/2 reduction,
// deg-7 sin / deg-8 cos minimax on |r| <= pi/4. Abs err ~1e-7.
// ---------------------------------------------------------------------------
__device__ __forceinline__ void sincos_poly(float x, float* sp, float* cp)
{
    float fq = rintf(x * 0.63661977236758134f);       // x * 2/pi
    int   q  = (int)fq;
    float r  = fmaf(-fq, 1.57079625129699707f, x);
    r        = fmaf(-fq, 7.54978941586159636e-8f, r);
    float r2 = r * r;

    float s = -1.9841271e-4f;
    s = fmaf(s, r2,  8.3333310e-3f);
    s = fmaf(s, r2, -1.6666667e-1f);
    s = fmaf(s * r2, r, r);

    float c =  2.44331571e-5f;
    c = fmaf(c, r2, -1.38873162e-3f);
    c = fmaf(c, r2,  4.16666418e-2f);
    c = fmaf(c, r2, -0.5f);
    c = fmaf(c, r2, 1.0f);

    float ss, cc;
    if (q & 1) { ss = c;  cc = -s; } else { ss = s; cc = c; }
    if (q & 2) { ss = -ss; cc = -cc; }
    *sp = ss; *cp = cc;
}

// ---------------------------------------------------------------------------
// K1: per-node prep. Trigger FIRST so the edge grid launches concurrently.
// ---------------------------------------------------------------------------
__global__ void __launch_bounds__(256) uv_kernel(
    const float* __restrict__ phase,
    const float* __restrict__ xy)
{
    pdl_trigger();
    int i = blockIdx.x * blockDim.x + threadIdx.x;
    if (i < N_NODES) {
        float s, c;
        sincos_poly(phase[i], &s, &c);
        float2 p = ((const float2*)xy)[i];
        g_uv[i]  = __floats2half2_rn(fmaf(c, p.x, s * p.y), fmaf(c, p.y, -s * p.x));
        g_sum[i] = make_float2(0.0f, 0.0f);
    }
}

// ---------------------------------------------------------------------------
// K2: fused edge pass, 8 edges/thread. Lower register pressure -> ~8 blocks/SM
// (vs 6 at EPT=16) so L1tex stays fed; gather pipeline otherwise identical to
// the best-measured R11/R12 version.
// ---------------------------------------------------------------------------
__global__ void __launch_bounds__(256) edge_kernel(
    const int* __restrict__ src,
    const int* __restrict__ dst)
{
    pdl_trigger();
    int t = blockIdx.x * blockDim.x + threadIdx.x;   // grid is exactly N_THREADS
    int lane = threadIdx.x & 31;
    int base = t * EPT;

    // Independent streaming loads (overlap with uv kernel via PDL)
    int4 s0 = __ldcs((const int4*)(src + base) + 0);
    int4 s1 = __ldcs((const int4*)(src + base) + 1);
    int4 d0 = __ldcs((const int4*)(dst + base) + 0);
    int4 d1 = __ldcs((const int4*)(dst + base) + 1);

    pdl_wait();   // g_uv / g_sum now visible

    int k[EPT]  = { s0.x, s0.y, s0.z, s0.w,  s1.x, s1.y, s1.z, s1.w };
    int di[EPT] = { d0.x, d0.y, d0.z, d0.w,  d1.x, d1.y, d1.z, d1.w };

    __half2 h[EPT];
    #pragma unroll
    for (int e = 0; e < EPT; e++) h[e] = __ldg(&g_uv[di[e]]);

    // Run-length scan over sorted keys; interior runs flush immediately
    int   cur = k[0];
    float2 f0 = __half22float2(h[0]);
    float U = f0.x, V = f0.y;
    #pragma unroll
    for (int e = 1; e < EPT; e++) {
        float2 f = __half22float2(h[e]);
        if (k[e] != cur) {
            atomicAdd(&g_sum[cur].x, U);
            atomicAdd(&g_sum[cur].y, V);
            cur = k[e];
            U = f.x; V = f.y;
        } else {
            U += f.x; V += f.y;
        }
    }

    // Warp segmented merge of pending runs (keys nondecreasing across lanes)
    #pragma unroll
    for (int o = 1; o < 32; o <<= 1) {
        int   pk = __shfl_up_sync(0xffffffffu, cur, o);
        float pU = __shfl_up_sync(0xffffffffu, U, o);
        float pV = __shfl_up_sync(0xffffffffu, V, o);
        if (lane >= o && pk == cur) { U += pU; V += pV; }
    }
    int nk = __shfl_down_sync(0xffffffffu, cur, 1);
    if (lane == 31 || nk != cur) {
        atomicAdd(&g_sum[cur].x, U);
        atomicAdd(&g_sum[cur].y, V);
    }
}

// ---------------------------------------------------------------------------
// K3: thread-per-node finalize. g_sum-independent math before the PDL wait.
// ---------------------------------------------------------------------------
__global__ void __launch_bounds__(256) finalize_kernel(
    const float* __restrict__ phase,
    const float* __restrict__ xy,
    const float* __restrict__ xy_dot_old,
    const float* __restrict__ w,
    const float* __restrict__ amp,
    const float* __restrict__ ha,
    float*       __restrict__ out)
{
    int i = blockIdx.x * blockDim.x + threadIdx.x;
    if (i >= N_NODES) { pdl_wait(); return; }

    float  ph = phase[i];
    float2 p  = ((const float2*)xy)[i];
    float2 pd = ((const float2*)xy_dot_old)[i];
    float  wi = w[i];
    float  am = amp[i];
    float  hi = ha[i];

    float s, c;
    sincos_poly(ph, &s, &c);

    float r2   = fmaf(p.x, p.x, p.y * p.y);
    float a    = ALPHA * (1.0f - r2 * r2);
    float zeta = 1.0f - hi * ((pd.x + EPS_) / (fabsf(pd.x) + EPS_));
    float b    = wi / (zeta + EPS_);
    float kx   = fmaf(a, p.x, -b * p.y);
    float ky   = fmaf(b, p.x,  a * p.y);

    pdl_wait();   // edge atomics visible
    float2 sv = g_sum[i];

    float sum_x = fmaf(c, sv.x, -s * sv.y);
    float sum_y = fmaf(s, sv.x,  c * sv.y);

    float x_dot = fminf(fmaxf(kx + sum_x, pd.x - DIFF_), pd.x + DIFF_);
    float y_dot = fminf(fmaxf(ky + sum_y, pd.y - DIFF_), pd.y + DIFF_);

    float xn = fmaf(x_dot, DT, p.x);
    float yn = fmaf(y_dot, DT, p.y);
    float ang = fminf(fmaxf(am * yn, -HARD), HARD);

    out[i] = ang;                                              // angles
    ((float2*)(out + N_NODES))[i]     = make_float2(xn, yn);   // xy_new
    ((float2*)(out + 3 * N_NODES))[i] = p;                     // xy_dot_old_new = xy
}

extern "C" void kernel_launch(void* const* d_in, const int* in_sizes, int n_in,
                              void* d_out, int out_size)
{
    const float* xy         = (const float*)d_in[0];
    const float* xy_dot_old = (const float*)d_in[1];
    const float* phase      = (const float*)d_in[2];
    const float* w          = (const float*)d_in[3];
    const float* amplitudes = (const float*)d_in[4];
    const float* ha         = (const float*)d_in[5];
    const int*   edge_src   = (const int*)d_in[6];
    const int*   edge_dst   = (const int*)d_in[7];
    float* out = (float*)d_out;

    int nb_nodes = (N_NODES + 255) / 256;
    int nb_edge  = N_THREADS / 256;          // 6250, exact

    cudaLaunchAttribute pdl_attr[1];
    pdl_attr[0].id = cudaLaunchAttributeProgrammaticStreamSerialization;
    pdl_attr[0].val.programmaticStreamSerializationAllowed = 1;

    uv_kernel<<<nb_nodes, 256>>>(phase, xy);

    {
        cudaLaunchConfig_t cfg = {};
        cfg.gridDim  = dim3(nb_edge);
        cfg.blockDim = dim3(256);
        cfg.stream   = 0;
        cfg.attrs    = pdl_attr;
        cfg.numAttrs = 1;
        cudaLaunchKernelEx(&cfg, edge_kernel, edge_src, edge_dst);
    }
    {
        cudaLaunchConfig_t cfg = {};
        cfg.gridDim  = dim3(nb_nodes);
        cfg.blockDim = dim3(256);
        cfg.stream   = 0;
        cfg.attrs    = pdl_attr;
        cfg.numAttrs = 1;
        cudaLaunchKernelEx(&cfg, finalize_kernel, phase, xy, xy_dot_old, w,
                           amplitudes, ha, out);
    }
}

// round 17
// speedup vs baseline: 1.3290x; 1.0006x over previous
#include <cuda_runtime.h>
#include <cuda_fp16.h>
#include <math.h>

#define N_NODES 200000
#define N_EDGES 12800000
#define ALPHA   0.1f
#define DT      0.01f
#define EPS_    1e-9f
#define DIFF_   10.0f
#define HARD    1.57079632679489662f

#define EPT        4                       // edges per thread (min useful)
#define N_THREADS  (N_EDGES / EPT)         // 3,200,000 = 12500 * 256 exactly

// Scratch (device globals — no allocation allowed)
__device__ __half2 g_uv[N_NODES];   // pre-rotated (u,v) = e^{-i phi}(x+iy)
__device__ float2  g_sum[N_NODES];  // per-node gathered sum, atomic-accumulated

__device__ __forceinline__ void pdl_wait()    { asm volatile("griddepcontrol.wait;" ::: "memory"); }
__device__ __forceinline__ void pdl_trigger() { asm volatile("griddepcontrol.launch_dependents;" ::: "memory"); }

// ---------------------------------------------------------------------------
// FMA-pipe sincos for |x| <= 2*pi (no MUFU). Cody-Waite pi/2 reduction,
// deg-7 sin / deg-8 cos minimax on |r| <= pi/4. Abs err ~1e-7.
// ---------------------------------------------------------------------------
__device__ __forceinline__ void sincos_poly(float x, float* sp, float* cp)
{
    float fq = rintf(x * 0.63661977236758134f);       // x * 2/pi
    int   q  = (int)fq;
    float r  = fmaf(-fq, 1.57079625129699707f, x);
    r        = fmaf(-fq, 7.54978941586159636e-8f, r);
    float r2 = r * r;

    float s = -1.9841271e-4f;
    s = fmaf(s, r2,  8.3333310e-3f);
    s = fmaf(s, r2, -1.6666667e-1f);
    s = fmaf(s * r2, r, r);

    float c =  2.44331571e-5f;
    c = fmaf(c, r2, -1.38873162e-3f);
    c = fmaf(c, r2,  4.16666418e-2f);
    c = fmaf(c, r2, -0.5f);
    c = fmaf(c, r2, 1.0f);

    float ss, cc;
    if (q & 1) { ss = c;  cc = -s; } else { ss = s; cc = c; }
    if (q & 2) { ss = -ss; cc = -cc; }
    *sp = ss; *cp = cc;
}

// ---------------------------------------------------------------------------
// K1: per-node prep. Trigger FIRST so the edge grid launches concurrently.
// ---------------------------------------------------------------------------
__global__ void __launch_bounds__(256) uv_kernel(
    const float* __restrict__ phase,
    const float* __restrict__ xy)
{
    pdl_trigger();
    int i = blockIdx.x * blockDim.x + threadIdx.x;
    if (i < N_NODES) {
        float s, c;
        sincos_poly(phase[i], &s, &c);
        float2 p = ((const float2*)xy)[i];
        g_uv[i]  = __floats2half2_rn(fmaf(c, p.x, s * p.y), fmaf(c, p.y, -s * p.x));
        g_sum[i] = make_float2(0.0f, 0.0f);
    }
}

// ---------------------------------------------------------------------------
// K2: fused edge pass, 4 edges/thread. Minimal register state -> maximal
// residency; gather pipeline otherwise identical to the proven version.
// ---------------------------------------------------------------------------
__global__ void __launch_bounds__(256) edge_kernel(
    const int* __restrict__ src,
    const int* __restrict__ dst)
{
    pdl_trigger();
    int t = blockIdx.x * blockDim.x + threadIdx.x;   // grid is exactly N_THREADS
    int lane = threadIdx.x & 31;
    int base = t * EPT;

    // Independent streaming loads (overlap with uv kernel via PDL)
    int4 s0 = __ldcs((const int4*)(src + base));
    int4 d0 = __ldcs((const int4*)(dst + base));

    pdl_wait();   // g_uv / g_sum now visible

    int k[EPT]  = { s0.x, s0.y, s0.z, s0.w };
    int di[EPT] = { d0.x, d0.y, d0.z, d0.w };

    __half2 h[EPT];
    #pragma unroll
    for (int e = 0; e < EPT; e++) h[e] = __ldg(&g_uv[di[e]]);

    // Run-length scan over sorted keys; interior runs flush immediately
    int   cur = k[0];
    float2 f0 = __half22float2(h[0]);
    float U = f0.x, V = f0.y;
    #pragma unroll
    for (int e = 1; e < EPT; e++) {
        float2 f = __half22float2(h[e]);
        if (k[e] != cur) {
            atomicAdd(&g_sum[cur].x, U);
            atomicAdd(&g_sum[cur].y, V);
            cur = k[e];
            U = f.x; V = f.y;
        } else {
            U += f.x; V += f.y;
        }
    }

    // Warp segmented merge of pending runs (keys nondecreasing across lanes)
    #pragma unroll
    for (int o = 1; o < 32; o <<= 1) {
        int   pk = __shfl_up_sync(0xffffffffu, cur, o);
        float pU = __shfl_up_sync(0xffffffffu, U, o);
        float pV = __shfl_up_sync(0xffffffffu, V, o);
        if (lane >= o && pk == cur) { U += pU; V += pV; }
    }
    int nk = __shfl_down_sync(0xffffffffu, cur, 1);
    if (lane == 31 || nk != cur) {
        atomicAdd(&g_sum[cur].x, U);
        atomicAdd(&g_sum[cur].y, V);
    }
}

// ---------------------------------------------------------------------------
// K3: thread-per-node finalize. g_sum-independent math before the PDL wait.
// ---------------------------------------------------------------------------
__global__ void __launch_bounds__(256) finalize_kernel(
    const float* __restrict__ phase,
    const float* __restrict__ xy,
    const float* __restrict__ xy_dot_old,
    const float* __restrict__ w,
    const float* __restrict__ amp,
    const float* __restrict__ ha,
    float*       __restrict__ out)
{
    int i = blockIdx.x * blockDim.x + threadIdx.x;
    if (i >= N_NODES) { pdl_wait(); return; }

    float  ph = phase[i];
    float2 p  = ((const float2*)xy)[i];
    float2 pd = ((const float2*)xy_dot_old)[i];
    float  wi = w[i];
    float  am = amp[i];
    float  hi = ha[i];

    float s, c;
    sincos_poly(ph, &s, &c);

    float r2   = fmaf(p.x, p.x, p.y * p.y);
    float a    = ALPHA * (1.0f - r2 * r2);
    float zeta = 1.0f - hi * ((pd.x + EPS_) / (fabsf(pd.x) + EPS_));
    float b    = wi / (zeta + EPS_);
    float kx   = fmaf(a, p.x, -b * p.y);
    float ky   = fmaf(b, p.x,  a * p.y);

    pdl_wait();   // edge atomics visible
    float2 sv = g_sum[i];

    float sum_x = fmaf(c, sv.x, -s * sv.y);
    float sum_y = fmaf(s, sv.x,  c * sv.y);

    float x_dot = fminf(fmaxf(kx + sum_x, pd.x - DIFF_), pd.x + DIFF_);
    float y_dot = fminf(fmaxf(ky + sum_y, pd.y - DIFF_), pd.y + DIFF_);

    float xn = fmaf(x_dot, DT, p.x);
    float yn = fmaf(y_dot, DT, p.y);
    float ang = fminf(fmaxf(am * yn, -HARD), HARD);

    out[i] = ang;                                              // angles
    ((float2*)(out + N_NODES))[i]     = make_float2(xn, yn);   // xy_new
    ((float2*)(out + 3 * N_NODES))[i] = p;                     // xy_dot_old_new = xy
}

extern "C" void kernel_launch(void* const* d_in, const int* in_sizes, int n_in,
                              void* d_out, int out_size)
{
    const float* xy         = (const float*)d_in[0];
    const float* xy_dot_old = (const float*)d_in[1];
    const float* phase      = (const float*)d_in[2];
    const float* w          = (const float*)d_in[3];
    const float* amplitudes = (const float*)d_in[4];
    const float* ha         = (const float*)d_in[5];
    const int*   edge_src   = (const int*)d_in[6];
    const int*   edge_dst   = (const int*)d_in[7];
    float* out = (float*)d_out;

    int nb_nodes = (N_NODES + 255) / 256;
    int nb_edge  = N_THREADS / 256;          // 12500, exact

    cudaLaunchAttribute pdl_attr[1];
    pdl_attr[0].id = cudaLaunchAttributeProgrammaticStreamSerialization;
    pdl_attr[0].val.programmaticStreamSerializationAllowed = 1;

    uv_kernel<<<nb_nodes, 256>>>(phase, xy);

    {
        cudaLaunchConfig_t cfg = {};
        cfg.gridDim  = dim3(nb_edge);
        cfg.blockDim = dim3(256);
        cfg.stream   = 0;
        cfg.attrs    = pdl_attr;
        cfg.numAttrs = 1;
        cudaLaunchKernelEx(&cfg, edge_kernel, edge_src, edge_dst);
    }
    {
        cudaLaunchConfig_t cfg = {};
        cfg.gridDim  = dim3(nb_nodes);
        cfg.blockDim = dim3(256);
        cfg.stream   = 0;
        cfg.attrs    = pdl_attr;
        cfg.numAttrs = 1;
        cudaLaunchKernelEx(&cfg, finalize_kernel, phase, xy, xy_dot_old, w,
                           amplitudes, ha, out);
    }
}